// round 8
// baseline (speedup 1.0000x reference)
#include <cuda_runtime.h>
#include <cuda_bf16.h>
#include <cstdint>
#include <math.h>

#define BATCH 4
#define SEQ 2048
#define RTOT (BATCH*SEQ)        // 8192 rows
#define INPUT_LEN 15
#define D_MODEL 256
#define N_LAYERS 4
#define D_INNER 512
#define D_STATE 16
#define D_CONV 4
#define DT_RANK 16
#define NC 64
#define CHUNK (SEQ/NC)          // 32
#define LN_EPS 1e-5f

// weight layer offsets in g_w3 (elements) -- [hi|lo] row stride 2K
#define WOFF_IN(l)  ((size_t)(l)*1024*512)
#define WOFF_OP(l)  ((size_t)2097152 + (size_t)(l)*256*1024)

// ---------------- persistent device scratch ----------------
__device__ float g_h  [RTOT*D_MODEL];
__device__ float g_res[RTOT*D_MODEL];
__device__ float g_xz [RTOT*2*D_INNER];
__device__ float g_xh [RTOT*D_INNER];
__device__ float g_dbl[RTOT*64];
__device__ float g_dt [RTOT*D_INNER];
__device__ float g_cP   [BATCH*D_INNER*D_STATE*NC];
__device__ float g_cH   [BATCH*D_INNER*D_STATE*NC];
__device__ float g_carry[BATCH*D_INNER*D_STATE*NC];
__device__ float g_xpT [N_LAYERS*512*64];                 // xproj transposed+padded
__device__ __align__(16) __nv_bfloat16 g_a3[RTOT*1024];   // activations [hi|lo]
__device__ __align__(16) __nv_bfloat16 g_w3[3145728];     // inproj+outproj weights [hi|lo]

// ---------------- helpers ----------------
__device__ __forceinline__ void cp16(void* smem, const void* g) {
    uint32_t s = (uint32_t)__cvta_generic_to_shared(smem);
    asm volatile("cp.async.cg.shared.global [%0], [%1], 16;" :: "r"(s), "l"(g));
}
#define CP_COMMIT() asm volatile("cp.async.commit_group;" ::: "memory")
#define CP_WAIT(N)  asm volatile("cp.async.wait_group %0;" :: "n"(N) : "memory")

__device__ __forceinline__ void ldm_x4(uint32_t& r0, uint32_t& r1, uint32_t& r2, uint32_t& r3,
                                       const void* p) {
    uint32_t a = (uint32_t)__cvta_generic_to_shared(p);
    asm volatile("ldmatrix.sync.aligned.m8n8.x4.shared.b16 {%0,%1,%2,%3}, [%4];"
                 : "=r"(r0), "=r"(r1), "=r"(r2), "=r"(r3) : "r"(a));
}
__device__ __forceinline__ void mma_bf16(float* c, const uint32_t* a, uint32_t b0, uint32_t b1) {
    asm volatile("mma.sync.aligned.m16n8k16.row.col.f32.bf16.bf16.f32 "
                 "{%0,%1,%2,%3}, {%4,%5,%6,%7}, {%8,%9}, {%0,%1,%2,%3};"
                 : "+f"(c[0]), "+f"(c[1]), "+f"(c[2]), "+f"(c[3])
                 : "r"(a[0]), "r"(a[1]), "r"(a[2]), "r"(a[3]), "r"(b0), "r"(b1));
}
__device__ __forceinline__ void split_bf16(float a, __nv_bfloat16& h, __nv_bfloat16& l) {
    h = __float2bfloat16(a);
    l = __float2bfloat16(a - __bfloat162float(h));
}

// ---------------- embed: h = x_src @ in_W^T (8 rows/block, W in smem) ----------------
__global__ __launch_bounds__(256) void embed_kernel(const float* __restrict__ x,
                                                    const float* __restrict__ W) {
    __shared__ float Ws[256*INPUT_LEN];
    __shared__ float xs[8][INPUT_LEN];
    int tid = threadIdx.x;
    int r0 = blockIdx.x*8;
#pragma unroll
    for (int i = 0; i < 15; i++) {
        int off = tid + i*256;
        if (off < 256*INPUT_LEN) Ws[off] = W[off];
    }
    if (tid < 8*INPUT_LEN) xs[tid/INPUT_LEN][tid%INPUT_LEN] = x[(size_t)(r0 + tid/INPUT_LEN)*INPUT_LEN + tid%INPUT_LEN];
    __syncthreads();
    int m = tid;
#pragma unroll
    for (int row = 0; row < 8; row++) {
        float acc = 0.f;
#pragma unroll
        for (int k = 0; k < INPUT_LEN; k++) acc += xs[row][k]*Ws[m*INPUT_LEN + k];
        g_h[(size_t)(r0+row)*D_MODEL + m] = acc;
    }
}

// ---------------- residual add + LN (warp per row) -> a3 [hi|lo] stride 512 ----------------
__global__ __launch_bounds__(256) void add_ln_kernel(const float* __restrict__ w,
                                                     const float* __restrict__ b, int first) {
    int wid = threadIdx.x >> 5, lane = threadIdx.x & 31;
    int r = blockIdx.x*8 + wid;
    float v[8], s = 0.f, s2 = 0.f;
#pragma unroll
    for (int k = 0; k < 8; k++) {
        int c = lane + k*32;
        float t = g_h[(size_t)r*D_MODEL + c];
        if (!first) t += g_res[(size_t)r*D_MODEL + c];
        g_res[(size_t)r*D_MODEL + c] = t;
        v[k] = t; s += t; s2 += t*t;
    }
#pragma unroll
    for (int o = 16; o > 0; o >>= 1) {
        s  += __shfl_xor_sync(0xffffffffu, s,  o);
        s2 += __shfl_xor_sync(0xffffffffu, s2, o);
    }
    float mean = s * (1.0f/D_MODEL);
    float var  = s2 * (1.0f/D_MODEL) - mean*mean;
    float rs = rsqrtf(var + LN_EPS);
#pragma unroll
    for (int k = 0; k < 8; k++) {
        int c = lane + k*32;
        float hn = (v[k] - mean)*rs*w[c] + b[c];
        __nv_bfloat16 h, l; split_bf16(hn, h, l);
        g_a3[(size_t)r*512 + c]       = h;
        g_a3[(size_t)r*512 + 256 + c] = l;
    }
}

// ---------------- weight conversion fp32 [N,K] -> [hi|lo] stride 2K ----------------
__global__ void convW_kernel(const float* __restrict__ W, __nv_bfloat16* __restrict__ dst,
                             int N, int K, size_t srcStride, size_t dstStride) {
    int l = blockIdx.y;
    int idx = blockIdx.x*256 + threadIdx.x;
    if (idx >= N*K) return;
    int n = idx / K, k = idx - n*K;
    float v = W[l*srcStride + (size_t)n*K + k];
    __nv_bfloat16 h, lo; split_bf16(v, h, lo);
    __nv_bfloat16* d = dst + l*dstStride + (size_t)n*(2*K);
    d[k]     = h;
    d[K + k] = lo;
}

// ---------------- xproj transpose+pad: [48,512] -> [512,64] ----------------
__global__ void xpT_kernel(const float* __restrict__ xproj) {
    int l = blockIdx.y;
    int idx = blockIdx.x*256 + threadIdx.x;     // 512*64
    if (idx >= 512*64) return;
    int k = idx >> 6, cc = idx & 63;
    float v = (cc < 48) ? xproj[(size_t)l*48*512 + (size_t)cc*512 + k] : 0.f;
    g_xpT[(size_t)l*512*64 + idx] = v;
}

// ---------------- HMMA GEMM (4-stage): C[M,N] = A "*" W^T via K-expansion ----------------
#define BK 32
#define PAD 8
#define LDSV (BK + PAD)          // 40
template<int BMT, int BN>
__global__ __launch_bounds__(256) void mma_gemm(
    const __nv_bfloat16* __restrict__ A2, const __nv_bfloat16* __restrict__ B2,
    float* __restrict__ C, int K, int ldc)
{
    extern __shared__ __nv_bfloat16 smem[];
    __nv_bfloat16* sA = smem;                      // [4][BMT*LDSV]
    __nv_bfloat16* sB = smem + 4*BMT*LDSV;         // [4][BN*LDSV]

    constexpr int MW = BMT/32;
    constexpr int NW = 8/MW;
    constexpr int WN = BN/NW;
    constexpr int NT = WN/8;

    const int tid = threadIdx.x;
    const int warp = tid >> 5, lane = tid & 31;
    const int m0 = blockIdx.y * BMT;
    const int n0 = blockIdx.x * BN;
    const int wm = (warp % MW) * 32;
    const int wn = (warp / MW) * WN;
    const int S = (3*K)/BK;

    auto load_stage = [&](int s, int buf) {
        int k3 = s*BK;
        int rg = k3 / K, off = k3 - rg*K;
        int srcA = (rg == 1) ? K + off : off;
        int srcB = (rg == 2) ? K + off : off;
        const __nv_bfloat16* Ag = A2 + (size_t)m0*(2*K) + srcA;
        int row = tid >> 2, ch = tid & 3;
        __nv_bfloat16* dA = sA + buf*(BMT*LDSV);
#pragma unroll
        for (int it = 0; it < BMT/64; it++) {
            int rr = row + it*64;
            cp16(&dA[rr*LDSV + ch*8], Ag + (size_t)rr*(2*K) + ch*8);
        }
        const __nv_bfloat16* Bg = B2 + (size_t)n0*(2*K) + srcB;
        __nv_bfloat16* dB = sB + buf*(BN*LDSV);
#pragma unroll
        for (int it = 0; it < BN/64; it++) {
            int rr = row + it*64;
            cp16(&dB[rr*LDSV + ch*8], Bg + (size_t)rr*(2*K) + ch*8);
        }
    };

    float acc[2][NT][4];
#pragma unroll
    for (int mi = 0; mi < 2; mi++)
#pragma unroll
        for (int nj = 0; nj < NT; nj++)
#pragma unroll
            for (int q = 0; q < 4; q++) acc[mi][nj][q] = 0.f;

    load_stage(0, 0); CP_COMMIT();
    load_stage(1, 1); CP_COMMIT();
    load_stage(2, 2); CP_COMMIT();

    const int lrow = lane & 15;
    const int lcol = (lane >> 4) * 8;

    for (int s = 0; s < S; s++) {
        if (s + 2 < S)      { CP_WAIT(2); }
        else if (s + 1 < S) { CP_WAIT(1); }
        else                { CP_WAIT(0); }
        __syncthreads();
        if (s + 3 < S) { load_stage(s + 3, (s + 3) & 3); CP_COMMIT(); }
        int buf = s & 3;
        const __nv_bfloat16* cA = sA + buf*(BMT*LDSV);
        const __nv_bfloat16* cB = sB + buf*(BN*LDSV);
#pragma unroll
        for (int kk = 0; kk < BK; kk += 16) {
            uint32_t a[2][4];
#pragma unroll
            for (int mi = 0; mi < 2; mi++)
                ldm_x4(a[mi][0], a[mi][1], a[mi][2], a[mi][3],
                       &cA[(wm + mi*16 + lrow)*LDSV + kk + lcol]);
            uint32_t b[NT][2];
#pragma unroll
            for (int np = 0; np < NT/2; np++) {
                uint32_t r0, r1, r2, r3;
                ldm_x4(r0, r1, r2, r3, &cB[(wn + np*16 + lrow)*LDSV + kk + lcol]);
                b[2*np][0] = r0; b[2*np+1][0] = r1;
                b[2*np][1] = r2; b[2*np+1][1] = r3;
            }
#pragma unroll
            for (int mi = 0; mi < 2; mi++)
#pragma unroll
                for (int nj = 0; nj < NT; nj++)
                    mma_bf16(acc[mi][nj], a[mi], b[nj][0], b[nj][1]);
        }
    }

    const int gid = lane >> 2, tig = lane & 3;
#pragma unroll
    for (int mi = 0; mi < 2; mi++) {
        int row = m0 + wm + mi*16 + gid;
#pragma unroll
        for (int nj = 0; nj < NT; nj++) {
            int col = n0 + wn + nj*8 + tig*2;
            *reinterpret_cast<float2*>(&C[(size_t)row*ldc + col]) =
                make_float2(acc[mi][nj][0], acc[mi][nj][1]);
            *reinterpret_cast<float2*>(&C[(size_t)(row+8)*ldc + col]) =
                make_float2(acc[mi][nj][2], acc[mi][nj][3]);
        }
    }
}

// ---------------- fused conv+SiLU + xproj + dt + scanA ----------------
// grid = BATCH*NC (256) blocks, 512 threads. smem: W_T 128KB + xh 64KB + dbl 8KB
__global__ __launch_bounds__(512) void fuse_mid_kernel(
    const float* __restrict__ cw, const float* __restrict__ cb,
    const float* __restrict__ xpT,
    const float* __restrict__ dtW, const float* __restrict__ dtb,
    const float* __restrict__ A_log)
{
    extern __shared__ float fs[];
    float* W_s   = fs;                       // [512*64] (k-major, 64 cols)
    float* xh_s  = fs + 512*64;              // [CHUNK][512]
    float* dbl_s = fs + 512*64 + CHUNK*512;  // [CHUNK][64]

    const int tid = threadIdx.x;
    const int b = blockIdx.x >> 6;
    const int c = blockIdx.x & (NC-1);
    const int t0 = c*CHUNK;

    // load xproj weights to smem (coalesced)
#pragma unroll
    for (int i = 0; i < 64; i++) W_s[i*512 + tid] = xpT[i*512 + tid];

    // ---- conv + SiLU ----
    const int d = tid;
    {
        float w0 = cw[d*4+0], w1 = cw[d*4+1], w2 = cw[d*4+2], w3 = cw[d*4+3];
        float bias = cb[d];
        const float* xzb = g_xz + ((size_t)b*SEQ)*1024 + d;
        float xm3 = (t0 >= 3) ? xzb[(size_t)(t0-3)*1024] : 0.f;
        float xm2 = (t0 >= 2) ? xzb[(size_t)(t0-2)*1024] : 0.f;
        float xm1 = (t0 >= 1) ? xzb[(size_t)(t0-1)*1024] : 0.f;
        for (int t = 0; t < CHUNK; t++) {
            float xt = xzb[(size_t)(t0+t)*1024];
            float a = bias + w0*xm3 + w1*xm2 + w2*xm1 + w3*xt;
            float xh = a / (1.f + __expf(-a));
            xh_s[t*512 + d] = xh;
            g_xh[(size_t)(b*SEQ + t0 + t)*D_INNER + d] = xh;
            xm3 = xm2; xm2 = xm1; xm1 = xt;
        }
    }
    __syncthreads();

    // ---- xproj (SIMT fp32): dbl[t][0..63] = xh[t] . W_s[:,c] ----
    {
        int tt = tid >> 4, sub = tid & 15, c0 = sub*4;
        float a0 = 0.f, a1 = 0.f, a2 = 0.f, a3v = 0.f;
        const float* xr = xh_s + tt*512;
#pragma unroll 8
        for (int k = 0; k < 512; k++) {
            float xv = xr[k];
            const float4 w = *reinterpret_cast<const float4*>(&W_s[k*64 + c0]);
            a0 += xv*w.x; a1 += xv*w.y; a2 += xv*w.z; a3v += xv*w.w;
        }
        float4 res = make_float4(a0, a1, a2, a3v);
        *reinterpret_cast<float4*>(&dbl_s[tt*64 + c0]) = res;
        *reinterpret_cast<float4*>(&g_dbl[(size_t)(b*SEQ + t0 + tt)*64 + c0]) = res;
    }
    __syncthreads();

    // ---- dt (softplus) + scanA ----
    {
        float wdt[DT_RANK];
#pragma unroll
        for (int k = 0; k < DT_RANK; k++) wdt[k] = dtW[d*DT_RANK + k];
        float bias2 = dtb[d];

        float Areg[D_STATE];
        bool structured = true;
#pragma unroll
        for (int n = 0; n < D_STATE; n++) {
            Areg[n] = -__expf(A_log[d*D_STATE + n]);
            structured = structured && (fabsf(Areg[n] + (float)(n+1)) < 1e-3f*(float)(n+1));
        }

        float hs[D_STATE], P[D_STATE];
#pragma unroll
        for (int n = 0; n < D_STATE; n++) { hs[n] = 0.f; P[n] = 1.f; }

        for (int t = 0; t < CHUNK; t++) {
            float lin = bias2;
#pragma unroll
            for (int k = 0; k < DT_RANK; k++) lin += wdt[k]*dbl_s[t*64 + k];
            float dt = (lin > 20.f) ? lin : log1pf(__expf(lin));
            g_dt[(size_t)(b*SEQ + t0 + t)*D_INNER + d] = dt;
            float x = xh_s[t*512 + d];
            float s = dt * x;
            if (structured) {
                float e = __expf(-dt);
                float da = e;
#pragma unroll
                for (int n = 0; n < D_STATE; n++) {
                    hs[n] = da*hs[n] + s*dbl_s[t*64 + 16 + n];
                    P[n] *= da;
                    da *= e;
                }
            } else {
#pragma unroll
                for (int n = 0; n < D_STATE; n++) {
                    float da = __expf(dt*Areg[n]);
                    hs[n] = da*hs[n] + s*dbl_s[t*64 + 16 + n];
                    P[n] *= da;
                }
            }
        }
        size_t base = ((size_t)(b*D_INNER + d)*D_STATE)*NC + c;
#pragma unroll
        for (int n = 0; n < D_STATE; n++) {
            g_cP[base + (size_t)n*NC] = P[n];
            g_cH[base + (size_t)n*NC] = hs[n];
        }
    }
}

// ---------------- scan pass B ----------------
__global__ void scanB_kernel() {
    int idx = blockIdx.x*blockDim.x + threadIdx.x;
    if (idx >= BATCH*D_INNER*D_STATE) return;
    size_t base = (size_t)idx * NC;
    float carry = 0.f;
#pragma unroll 4
    for (int c = 0; c < NC; c++) {
        g_carry[base + c] = carry;
        carry = g_cP[base + c]*carry + g_cH[base + c];
    }
}

// ---------------- scan pass C: replay + D-skip + SiLU gate -> a3 [hi|lo] stride 1024 ----------------
__global__ __launch_bounds__(128) void scanC_kernel(const float* __restrict__ A_log,
                                                    const float* __restrict__ Dp) {
    int gid = blockIdx.x;                 // B*NC*4 = 1024
    int db = gid & 3;
    int c  = (gid >> 2) & (NC-1);
    int b  = gid >> 8;
    int d  = db*128 + threadIdx.x;
    int t0 = c * CHUNK;

    __shared__ float sB[CHUNK][D_STATE];
    __shared__ float sC[CHUNK][D_STATE];
    for (int i = threadIdx.x; i < CHUNK*D_STATE; i += 128) {
        int t = i >> 4, n = i & 15;
        size_t row = ((size_t)(b*SEQ + t0 + t))*64;
        sB[t][n] = g_dbl[row + 16 + n];
        sC[t][n] = g_dbl[row + 32 + n];
    }
    __syncthreads();

    float Areg[D_STATE];
    bool structured = true;
#pragma unroll
    for (int n = 0; n < D_STATE; n++) {
        Areg[n] = -__expf(A_log[d*D_STATE + n]);
        structured = structured && (fabsf(Areg[n] + (float)(n+1)) < 1e-3f*(float)(n+1));
    }

    float hs[D_STATE];
    size_t base = ((size_t)(b*D_INNER + d)*D_STATE)*NC + c;
#pragma unroll
    for (int n = 0; n < D_STATE; n++) hs[n] = g_carry[base + (size_t)n*NC];

    float Dd = Dp[d];
    const float* dtp = &g_dt[(size_t)(b*SEQ + t0)*D_INNER + d];
    const float* xp  = &g_xh[(size_t)(b*SEQ + t0)*D_INNER + d];
    const float* zp  = &g_xz[(size_t)(b*SEQ + t0)*(2*D_INNER) + D_INNER + d];
    __nv_bfloat16* yp = &g_a3[(size_t)(b*SEQ + t0)*1024 + d];

    for (int t = 0; t < CHUNK; t++) {
        float dt = dtp[(size_t)t*D_INNER];
        float x  = xp [(size_t)t*D_INNER];
        float s = dt * x;
        float y = 0.f;
        if (structured) {
            float e = __expf(-dt);
            float da = e;
#pragma unroll
            for (int n = 0; n < D_STATE; n++) {
                hs[n] = da*hs[n] + s*sB[t][n];
                y += hs[n]*sC[t][n];
                da *= e;
            }
        } else {
#pragma unroll
            for (int n = 0; n < D_STATE; n++) {
                float da = __expf(dt*Areg[n]);
                hs[n] = da*hs[n] + s*sB[t][n];
                y += hs[n]*sC[t][n];
            }
        }
        y += Dd * x;
        float z = zp[(size_t)t*(2*D_INNER)];
        y *= z / (1.f + __expf(-z));
        __nv_bfloat16 h, l; split_bf16(y, h, l);
        yp[(size_t)t*1024]       = h;
        yp[(size_t)t*1024 + 512] = l;
    }
}

// ---------------- head ----------------
__global__ void head_kernel(const float* __restrict__ Wout, float* __restrict__ out) {
    int r = blockIdx.x*8 + (threadIdx.x >> 5);
    int lane = threadIdx.x & 31;
    float acc = 0.f;
#pragma unroll
    for (int k = 0; k < 8; k++)
        acc += g_h[(size_t)r*D_MODEL + lane + k*32] * Wout[lane + k*32];
#pragma unroll
    for (int o = 16; o > 0; o >>= 1) acc += __shfl_xor_sync(0xffffffffu, acc, o);
    if (lane == 0) out[r] = acc;
}

// ---------------- driver ----------------
extern "C" void kernel_launch(void* const* d_in, const int* in_sizes, int n_in,
                              void* d_out, int out_size)
{
    const float* x_src  = (const float*)d_in[0];
    const float* in_W   = (const float*)d_in[2];
    const float* norm_w = (const float*)d_in[3];
    const float* norm_b = (const float*)d_in[4];
    const float* inproj = (const float*)d_in[5];
    const float* conv_w = (const float*)d_in[6];
    const float* conv_b = (const float*)d_in[7];
    const float* xproj  = (const float*)d_in[8];
    const float* dtW    = (const float*)d_in[9];
    const float* dtb    = (const float*)d_in[10];
    const float* A_log  = (const float*)d_in[11];
    const float* Dp     = (const float*)d_in[12];
    const float* outproj= (const float*)d_in[13];
    const float* outW   = (const float*)d_in[14];

    float *p_xz, *p_h, *p_xpT;
    __nv_bfloat16 *p_a3, *p_w3;
    cudaGetSymbolAddress((void**)&p_xz,  g_xz);
    cudaGetSymbolAddress((void**)&p_h,   g_h);
    cudaGetSymbolAddress((void**)&p_a3,  g_a3);
    cudaGetSymbolAddress((void**)&p_w3,  g_w3);
    cudaGetSymbolAddress((void**)&p_xpT, g_xpT);

    const int SM_128_128 = 4*(128+128)*LDSV*2;   // 81920
    const int SM_64_128  = 4*(64+128)*LDSV*2;    // 61440
    const int SM_FUSE    = (512*64 + CHUNK*512 + CHUNK*64)*4;  // 204800
    cudaFuncSetAttribute(mma_gemm<128,128>, cudaFuncAttributeMaxDynamicSharedMemorySize, SM_128_128);
    cudaFuncSetAttribute(mma_gemm<64,128>,  cudaFuncAttributeMaxDynamicSharedMemorySize, SM_64_128);
    cudaFuncSetAttribute(fuse_mid_kernel,   cudaFuncAttributeMaxDynamicSharedMemorySize, SM_FUSE);

    // one-time weight preps
    convW_kernel<<<dim3(1024, N_LAYERS), 256>>>(inproj,  p_w3 + WOFF_IN(0), 1024, 256,
                                                (size_t)1024*256, (size_t)1024*512);
    convW_kernel<<<dim3(512,  N_LAYERS), 256>>>(outproj, p_w3 + WOFF_OP(0), 256, 512,
                                                (size_t)256*512, (size_t)256*1024);
    xpT_kernel<<<dim3(128, N_LAYERS), 256>>>(xproj);

    embed_kernel<<<RTOT/8, 256>>>(x_src, in_W);

    for (int l = 0; l < N_LAYERS; l++) {
        add_ln_kernel<<<RTOT/8, 256>>>(norm_w + l*D_MODEL, norm_b + l*D_MODEL, l == 0);

        // in_proj: (M=8192, N=1024, K=256)
        mma_gemm<128,128><<<dim3(8, 64), 256, SM_128_128>>>(
            p_a3, p_w3 + WOFF_IN(l), p_xz, 256, 1024);

        fuse_mid_kernel<<<BATCH*NC, 512, SM_FUSE>>>(
            conv_w + (size_t)l*D_INNER*D_CONV, conv_b + l*D_INNER,
            p_xpT + (size_t)l*512*64,
            dtW + (size_t)l*D_INNER*DT_RANK, dtb + l*D_INNER,
            A_log + (size_t)l*D_INNER*D_STATE);

        scanB_kernel<<<(BATCH*D_INNER*D_STATE)/256, 256>>>();
        scanC_kernel<<<BATCH*NC*4, 128>>>(A_log + (size_t)l*D_INNER*D_STATE,
                                          Dp + l*D_INNER);

        // out_proj: (M=8192, N=256, K=512)
        mma_gemm<64,128><<<dim3(2, 128), 256, SM_64_128>>>(
            p_a3, p_w3 + WOFF_OP(l), p_h, 512, 256);
    }

    head_kernel<<<RTOT/8, 256>>>(outW, (float*)d_out);
}